// round 15
// baseline (speedup 1.0000x reference)
#include <cuda_runtime.h>
#include <cuda_bf16.h>
#include <math.h>
#include <stdint.h>

#define HWSZ 16384
#define IMG  128

// -------- scratch (static device memory; no runtime allocation) ------------
#define BUF64 8388608ull   // 8*64*16384 floats
#define BUF72 9437184ull
#define SBUF  73728ull     // per-(b,c,w) softmax stats: 8*72*128
static __device__ float g_scratch[4*BUF64 + BUF72 + 2*SBUF];

// ===================== bf16 split-precision MMA helpers =====================
static __device__ __forceinline__ float lrelu(float v){ return v > 0.f ? v : 0.1f*v; }

static __device__ __forceinline__ void bfsplit2(float v0, float v1,
                                                uint32_t& hi, uint32_t& lo){
    __nv_bfloat16 h0 = __float2bfloat16(v0), h1 = __float2bfloat16(v1);
    float r0 = v0 - __bfloat162float(h0);
    float r1 = v1 - __bfloat162float(h1);
    __nv_bfloat162 H = __halves2bfloat162(h0, h1);
    __nv_bfloat162 L = __halves2bfloat162(__float2bfloat16(r0), __float2bfloat16(r1));
    hi = *(uint32_t*)&H;  lo = *(uint32_t*)&L;
}

static __device__ __forceinline__ void mma_bf16(float* c, const uint32_t* a,
                                                uint32_t b0, uint32_t b1){
    asm volatile(
        "mma.sync.aligned.m16n8k16.row.col.f32.bf16.bf16.f32 "
        "{%0,%1,%2,%3}, {%4,%5,%6,%7}, {%8,%9}, {%0,%1,%2,%3};"
        : "+f"(c[0]), "+f"(c[1]), "+f"(c[2]), "+f"(c[3])
        : "r"(a[0]), "r"(a[1]), "r"(a[2]), "r"(a[3]), "r"(b0), "r"(b1));
}

template<int NT>
static __device__ __forceinline__ void mma_chunk(
    const uint32_t* __restrict__ sAh, const uint32_t* __restrict__ sAl,
    const uint32_t* __restrict__ sBh, const uint32_t* __restrict__ sBl,
    int pr, int gid, int tig, float (*acc)[4])
{
    #pragma unroll
    for (int kh = 0; kh < 2; kh++) {
        const int ab = kh*8 + tig;
        uint32_t ah[4], al[4];
        ah[0] = sAh[pr*20 + ab];       ah[1] = sAh[(pr+8)*20 + ab];
        ah[2] = sAh[pr*20 + ab + 4];   ah[3] = sAh[(pr+8)*20 + ab + 4];
        al[0] = sAl[pr*20 + ab];       al[1] = sAl[(pr+8)*20 + ab];
        al[2] = sAl[pr*20 + ab + 4];   al[3] = sAl[(pr+8)*20 + ab + 4];
        #pragma unroll
        for (int nt = 0; nt < NT; nt++) {
            const int nb = (nt*8 + gid)*20 + kh*8 + tig;
            uint32_t bh0 = sBh[nb], bh1 = sBh[nb + 4];
            uint32_t bl0 = sBl[nb], bl1 = sBl[nb + 4];
            mma_bf16(acc[nt], ah, bh0, bh1);
            mma_bf16(acc[nt], al, bh0, bh1);
            mma_bf16(acc[nt], ah, bl0, bl1);
        }
    }
}

// -------- register-pipelined chunk loaders (overlap gmem with MMA) ---------
template<int SPLIT, int C1>
static __device__ __forceinline__ void load_a_regs(
    float* av0, float* av1, const float* __restrict__ in0,
    const float* __restrict__ in1, int c0, int bat, int p0, int tid)
{
    #pragma unroll
    for (int i = 0; i < 8; i++) {
        int idx = tid + 256*i;
        int k2 = idx >> 7, p = idx & 127;
        int kg = c0 + 2*k2;
        const float* s = (kg < SPLIT)
            ? in0 + ((size_t)bat*SPLIT + kg)*HWSZ
            : in1 + ((size_t)bat*C1 + (kg - SPLIT))*HWSZ;
        av0[i] = s[p0 + p];  av1[i] = s[p0 + p + HWSZ];
    }
}
template<int N, int KC>
static __device__ __forceinline__ void load_b_regs(
    float* bv0, float* bv1, const float* __restrict__ W, int c0, int tid)
{
    #pragma unroll
    for (int i = 0; i < N/16; i++) {
        int idx = tid + 256*i;
        int n = idx >> 4, k2 = idx & 15;
        bv0[i] = W[n*KC + c0 + 2*k2];  bv1[i] = W[n*KC + c0 + 2*k2 + 1];
    }
}
template<int N>
static __device__ __forceinline__ void store_regs_split(
    uint32_t* sAh, uint32_t* sAl, uint32_t* sBh, uint32_t* sBl,
    const float* av0, const float* av1, const float* bv0, const float* bv1,
    int tid)
{
    #pragma unroll
    for (int i = 0; i < 8; i++) {
        int idx = tid + 256*i;
        int k2 = idx >> 7, p = idx & 127;
        uint32_t hi, lo; bfsplit2(av0[i], av1[i], hi, lo);
        sAh[p*20 + k2] = hi;  sAl[p*20 + k2] = lo;
    }
    #pragma unroll
    for (int i = 0; i < N/16; i++) {
        int idx = tid + 256*i;
        int n = idx >> 4, k2 = idx & 15;
        uint32_t hi, lo; bfsplit2(bv0[i], bv1[i], hi, lo);
        sBh[n*20 + k2] = hi;  sBl[n*20 + k2] = lo;
    }
}

// legacy direct loaders (used by embed stage-2 B)
static __device__ __forceinline__ void load_b_chunk(
    uint32_t* sBh, uint32_t* sBl, const float* __restrict__ W,
    int N, int KC, int c0, int tid)
{
    for (int idx = tid; idx < N*16; idx += 256) {
        int n = idx >> 4, k2 = idx & 15;
        float v0 = W[n*KC + c0 + 2*k2], v1 = W[n*KC + c0 + 2*k2 + 1];
        uint32_t hi, lo; bfsplit2(v0, v1, hi, lo);
        sBh[n*20 + k2] = hi;  sBl[n*20 + k2] = lo;
    }
}

// ---------------------------------------------------------------------------
// Pipelined 1x1-conv GEMM (bf16 split, tensor cores). CTA: 128 px x N couts.
// Register double-buffer: next chunk's gmem loads issue before the MMA burst.
// ---------------------------------------------------------------------------
template<int KC, int N, int SPLIT, int ACT>
__global__ void __launch_bounds__(256, 3)
conv1x1_bf16(const float* __restrict__ in0, const float* __restrict__ in1,
             const float* __restrict__ w0, const float* __restrict__ w1,
             const float* __restrict__ w2,
             const float* __restrict__ b0, const float* __restrict__ b1,
             const float* __restrict__ b2,
             float* __restrict__ o0, float* __restrict__ o1, float* __restrict__ o2)
{
    static_assert(N % 16 == 0, "pipelined B loader needs N%16==0");
    constexpr int NT = N/8;
    constexpr int NP = N + 2;
    constexpr int AB = (256 + 2*N)*80;
    constexpr int ST = 128*NP*4;
    constexpr int SMEMB = AB > ST ? AB : ST;
    __shared__ __align__(16) char smem[SMEMB];
    uint32_t* sAh = (uint32_t*)smem;
    uint32_t* sAl = sAh + 128*20;
    uint32_t* sBh = sAl + 128*20;
    uint32_t* sBl = sBh + N*20;
    float* sOut = (float*)smem;

    const int tid = threadIdx.x;
    const int warp = tid >> 5, lane = tid & 31;
    const int gid = lane >> 2, tig = lane & 3;
    const int bat = blockIdx.y, p0 = blockIdx.x*128, seg = blockIdx.z;
    const int pr = warp*16 + gid;

    const float* W  = (seg == 0) ? w0 : (seg == 1) ? w1 : w2;
    const float* Bb = (seg == 0) ? b0 : (seg == 1) ? b1 : b2;
    float*       O  = (seg == 0) ? o0 : (seg == 1) ? o1 : o2;

    float acc[NT][4];
    #pragma unroll
    for (int t = 0; t < NT; t++)
        #pragma unroll
        for (int j = 0; j < 4; j++) acc[t][j] = 0.f;

    float av0[8], av1[8], bv0[N/16], bv1[N/16];
    load_a_regs<SPLIT, KC-SPLIT>(av0, av1, in0, in1, 0, bat, p0, tid);
    load_b_regs<N, KC>(bv0, bv1, W, 0, tid);

    for (int c0 = 0; c0 < KC; c0 += 32) {
        store_regs_split<N>(sAh, sAl, sBh, sBl, av0, av1, bv0, bv1, tid);
        __syncthreads();
        if (c0 + 32 < KC) {   // issue next chunk's loads; they fly during MMA
            load_a_regs<SPLIT, KC-SPLIT>(av0, av1, in0, in1, c0+32, bat, p0, tid);
            load_b_regs<N, KC>(bv0, bv1, W, c0+32, tid);
        }
        mma_chunk<NT>(sAh, sAl, sBh, sBl, pr, gid, tig, acc);
        __syncthreads();
    }

    #pragma unroll
    for (int nt = 0; nt < NT; nt++) {
        int n = nt*8 + 2*tig;
        sOut[pr*NP + n]     = acc[nt][0];  sOut[pr*NP + n + 1]     = acc[nt][1];
        sOut[(pr+8)*NP + n] = acc[nt][2];  sOut[(pr+8)*NP + n + 1] = acc[nt][3];
    }
    __syncthreads();
    for (int idx = tid; idx < N*128; idx += 256) {
        int n = idx >> 7, p = idx & 127;
        float v = sOut[p*NP + n] + (Bb ? Bb[n] : 0.f);
        if (ACT) v = lrelu(v);
        O[((size_t)bat*N + n)*HWSZ + p0 + p] = v;
    }
}

// ---------------------------------------------------------------------------
// Fused embed chain: O[72] = W2 * lrelu(W1 * [in0;in1]) + b2.
// Stage-1 loop register-pipelined like conv1x1.
// ---------------------------------------------------------------------------
__global__ void __launch_bounds__(256, 4)
embed_fused_kernel(const float* __restrict__ in0, const float* __restrict__ in1,
                   const float* __restrict__ W1, const float* __restrict__ W2,
                   const float* __restrict__ b2, float* __restrict__ O)
{
    __shared__ __align__(16) char smem[37888];
    uint32_t* sAh  = (uint32_t*)smem;
    uint32_t* sAl  = sAh + 128*20;
    uint32_t* sB1h = sAl + 128*20;
    uint32_t* sB1l = sB1h + 32*20;
    uint32_t* sB2h = sAl + 128*20;       // aliases stage-1 B (dead by then)
    uint32_t* sB2l = sB2h + 72*20;
    float* sOut = (float*)smem;

    const int tid = threadIdx.x;
    const int warp = tid >> 5, lane = tid & 31;
    const int gid = lane >> 2, tig = lane & 3;
    const int bat = blockIdx.y, p0 = blockIdx.x*128;
    const int pr = warp*16 + gid;

    float acc1[4][4];
    #pragma unroll
    for (int t = 0; t < 4; t++)
        #pragma unroll
        for (int j = 0; j < 4; j++) acc1[t][j] = 0.f;

    float av0[8], av1[8], bv0[2], bv1[2];
    load_a_regs<64, 64>(av0, av1, in0, in1, 0, bat, p0, tid);
    load_b_regs<32, 128>(bv0, bv1, W1, 0, tid);

    for (int c0 = 0; c0 < 128; c0 += 32) {
        store_regs_split<32>(sAh, sAl, sB1h, sB1l, av0, av1, bv0, bv1, tid);
        __syncthreads();
        if (c0 + 32 < 128) {
            load_a_regs<64, 64>(av0, av1, in0, in1, c0+32, bat, p0, tid);
            load_b_regs<32, 128>(bv0, bv1, W1, c0+32, tid);
        }
        mma_chunk<4>(sAh, sAl, sB1h, sB1l, pr, gid, tig, acc1);
        __syncthreads();
    }

    #pragma unroll
    for (int nt = 0; nt < 4; nt++) {
        uint32_t hi, lo;
        bfsplit2(lrelu(acc1[nt][0]), lrelu(acc1[nt][1]), hi, lo);
        sAh[pr*20 + nt*4 + tig] = hi;  sAl[pr*20 + nt*4 + tig] = lo;
        bfsplit2(lrelu(acc1[nt][2]), lrelu(acc1[nt][3]), hi, lo);
        sAh[(pr+8)*20 + nt*4 + tig] = hi;  sAl[(pr+8)*20 + nt*4 + tig] = lo;
    }
    load_b_chunk(sB2h, sB2l, W2, 72, 32, 0, tid);
    __syncthreads();

    float acc2[9][4];
    #pragma unroll
    for (int t = 0; t < 9; t++)
        #pragma unroll
        for (int j = 0; j < 4; j++) acc2[t][j] = 0.f;
    mma_chunk<9>(sAh, sAl, sB2h, sB2l, pr, gid, tig, acc2);
    __syncthreads();

    #pragma unroll
    for (int nt = 0; nt < 9; nt++) {
        int n = nt*8 + 2*tig;
        sOut[pr*74 + n]     = acc2[nt][0];  sOut[pr*74 + n + 1]     = acc2[nt][1];
        sOut[(pr+8)*74 + n] = acc2[nt][2];  sOut[(pr+8)*74 + n + 1] = acc2[nt][3];
    }
    __syncthreads();
    for (int idx = tid; idx < 72*128; idx += 256) {
        int n = idx >> 7, p = idx & 127;
        float v = sOut[p*74 + n] + b2[n];
        O[((size_t)bat*72 + n)*HWSZ + p0 + p] = v;
    }
}

// ---------------------------------------------------------------------------
// Grouped 3x3 conv (groups=4, 16 in/16 out per group), pad 1, + leaky relu.
// ---------------------------------------------------------------------------
__global__ void __launch_bounds__(256, 5)
convke_kernel(float* __restrict__ out, const float* __restrict__ in,
              const float* __restrict__ w)
{
    const int tid = threadIdx.x;
    const int b = blockIdx.z >> 2, g = blockIdx.z & 3;
    const int x0 = blockIdx.x * 16, y0 = blockIdx.y * 16;
    __shared__ __align__(16) float sv[16][18][18];
    __shared__ __align__(16) float swt[16][9][16];

    for (int i = tid; i < 16*16*9; i += 256) {
        int co = i / 144; int r = i - co*144; int ci = r / 9; int tap = r - ci*9;
        swt[ci][tap][co] = w[((g*16 + co)*16 + ci)*9 + tap];
    }
    for (int i = tid; i < 16*324; i += 256) {
        int ci = i / 324; int r = i - ci*324; int yy = r / 18; int xx = r - yy*18;
        int gy = y0 + yy - 1, gx = x0 + xx - 1;
        float v = 0.f;
        if ((unsigned)gy < 128u && (unsigned)gx < 128u)
            v = in[(((size_t)b*64 + g*16 + ci)*IMG + gy)*IMG + gx];
        sv[ci][yy][xx] = v;
    }
    __syncthreads();

    const int ty = tid >> 4, tx = tid & 15;
    float acc[16];
    #pragma unroll
    for (int c = 0; c < 16; c++) acc[c] = 0.f;

    #pragma unroll
    for (int ci = 0; ci < 16; ci++) {
        float win[9];
        #pragma unroll
        for (int t = 0; t < 9; t++) win[t] = sv[ci][ty + t/3][tx + t%3];
        #pragma unroll
        for (int t = 0; t < 9; t++) {
            #pragma unroll
            for (int q = 0; q < 4; q++) {
                float4 wq = *(const float4*)&swt[ci][t][q*4];
                acc[q*4+0] += win[t]*wq.x;
                acc[q*4+1] += win[t]*wq.y;
                acc[q*4+2] += win[t]*wq.z;
                acc[q*4+3] += win[t]*wq.w;
            }
        }
    }
    #pragma unroll
    for (int co = 0; co < 16; co++) {
        float v = acc[co]; v = v > 0.f ? v : 0.1f*v;
        out[(((size_t)b*64 + g*16 + co)*IMG + y0+ty)*IMG + x0+tx] = v;
    }
}

// ---------------------------------------------------------------------------
// Softmax column stats: per (b,c,w) max and 1/sum(exp(.-max)) over H.
// ---------------------------------------------------------------------------
__global__ void softmax_stats_kernel(const float* __restrict__ a,
                                     float* __restrict__ gmax,
                                     float* __restrict__ ginv)
{
    const int tx = threadIdx.x, ty = threadIdx.y;
    const int w = blockIdx.x*32 + tx;
    const size_t base = (size_t)blockIdx.y * HWSZ + w;   // blockIdx.y = b*72+c
    float vals[16];
    float mx = -3.4e38f;
    #pragma unroll
    for (int i = 0; i < 16; i++) {
        vals[i] = a[base + (size_t)(ty*16 + i)*IMG];
        mx = fmaxf(mx, vals[i]);
    }
    __shared__ float red[8][32];
    red[ty][tx] = mx;
    __syncthreads();
    float m = red[0][tx];
    #pragma unroll
    for (int j = 1; j < 8; j++) m = fmaxf(m, red[j][tx]);
    __syncthreads();
    float s = 0.f;
    #pragma unroll
    for (int i = 0; i < 16; i++) s += __expf(vals[i] - m);
    red[ty][tx] = s;
    __syncthreads();
    if (ty == 0) {
        float tot = 0.f;
        #pragma unroll
        for (int j = 0; j < 8; j++) tot += red[j][tx];
        gmax[(size_t)blockIdx.y*IMG + w] = m;
        ginv[(size_t)blockIdx.y*IMG + w] = 1.f / tot;
    }
}

// ---------------------------------------------------------------------------
// Per-pixel dynamic local conv v3 (32x16 tile, 2 px/thread, occupancy-tuned).
// RESID instance applies softmax normalization (exp(raw-m)*inv) + residual.
// ---------------------------------------------------------------------------
template<bool RESID>
__global__ void __launch_bounds__(256, 6)
localconv_kernel(float* __restrict__ out, const float* __restrict__ v,
                 const float* __restrict__ wd, const float* __restrict__ resid,
                 const float* __restrict__ gmax, const float* __restrict__ ginv)
{
    const int tid = threadIdx.x;
    const int b = blockIdx.z >> 3, cg = blockIdx.z & 7;
    const int x0 = blockIdx.x * 32, y0 = blockIdx.y * 16;
    __shared__ float sv[8][18][35];

    const float* vb = v + ((size_t)(b*64 + cg*8))*HWSZ;
    #pragma unroll
    for (int cl = 0; cl < 8; cl++) {
        for (int i = tid; i < 18*34; i += 256) {
            int yy = i / 34, xx = i - yy*34;
            int gy = y0 + yy - 1, gx = x0 + xx - 1;
            float val = 0.f;
            if ((unsigned)gy < 128u && (unsigned)gx < 128u)
                val = vb[cl*HWSZ + gy*IMG + gx];
            sv[cl][yy][xx] = val;
        }
    }
    __syncthreads();

    const int ty = tid >> 4;            // 0..15
    const int tx = (tid & 15) * 2;      // 0,2,...,30
    const size_t pix = (size_t)(y0 + ty)*IMG + (x0 + tx);

    float2 wt[9];
    const float* wb = wd + ((size_t)(b*72 + cg*9))*HWSZ + pix;
    #pragma unroll
    for (int t = 0; t < 9; t++)
        wt[t] = *(const float2*)(wb + (size_t)t*HWSZ);

    if (RESID) {
        const size_t sb = (size_t)(b*72 + cg*9)*IMG + (x0 + tx);
        #pragma unroll
        for (int t = 0; t < 9; t++) {
            const float2 m  = *(const float2*)(gmax + sb + (size_t)t*IMG);
            const float2 iv = *(const float2*)(ginv + sb + (size_t)t*IMG);
            wt[t].x = __expf(wt[t].x - m.x) * iv.x;
            wt[t].y = __expf(wt[t].y - m.y) * iv.y;
        }
    }

    float* ob = out + ((size_t)(b*64 + cg*8))*HWSZ + pix;
    const float* rb = RESID ? resid + ((size_t)(b*64 + cg*8))*HWSZ + pix : nullptr;

    #pragma unroll
    for (int cl = 0; cl < 8; cl++) {
        float a0 = 0.f, a1 = 0.f;
        #pragma unroll
        for (int r = 0; r < 3; r++) {
            float vr[4];
            #pragma unroll
            for (int j = 0; j < 4; j++) vr[j] = sv[cl][ty + r][tx + j];
            #pragma unroll
            for (int c = 0; c < 3; c++) {
                const float2 w = wt[r*3 + c];
                a0 += vr[c]     * w.x;
                a1 += vr[c + 1] * w.y;
            }
        }
        float2 o = make_float2(a0, a1);
        if (RESID) {
            const float2 rr = *(const float2*)(rb + (size_t)cl*HWSZ);
            o.x += rr.x; o.y += rr.y;
        }
        *(float2*)(ob + (size_t)cl*HWSZ) = o;
    }
}

// ---------------------------------------------------------------------------
extern "C" void kernel_launch(void* const* d_in, const int* in_sizes, int n_in,
                              void* d_out, int out_size)
{
    const float* x      = (const float*)d_in[0];
    const float* phi_w  = (const float*)d_in[1];
    const float* phi_b  = (const float*)d_in[2];
    const float* theta_w= (const float*)d_in[3];
    const float* theta_b= (const float*)d_in[4];
    const float* ke_w   = (const float*)d_in[5];
    const float* e1_w   = (const float*)d_in[6];
    const float* e2_w   = (const float*)d_in[7];
    const float* e2_b   = (const float*)d_in[8];
    const float* c1_w   = (const float*)d_in[9];
    const float* sw1_w  = (const float*)d_in[10];
    const float* sw2_w  = (const float*)d_in[11];
    const float* sw2_b  = (const float*)d_in[12];
    const float* sec_w  = (const float*)d_in[13];
    const float* sec_b  = (const float*)d_in[14];
    float* out = (float*)d_out;

    float* base = nullptr;
    cudaGetSymbolAddress((void**)&base, g_scratch);
    float* q      = base;              // -> lc
    float* v      = base + BUF64;
    float* keypre = base + 2*BUF64;    // -> u
    float* key    = base + 3*BUF64;
    float* w72    = base + 4*BUF64;    // -> attn(raw)
    float* gmax   = base + 4*BUF64 + BUF72;
    float* ginv   = gmax + SBUF;
    float* lc   = q;
    float* u    = keypre;
    float* attn = w72;

    // fused (by grid.z): keypre = phi(x)+b | q = theta(x)+b | v = c1(x)
    conv1x1_bf16<64,64,64,0><<<dim3(128,8,3),256>>>(
        x, nullptr, phi_w, theta_w, c1_w, phi_b, theta_b, nullptr,
        keypre, q, v);
    // key = lrelu(grouped 3x3(keypre))
    convke_kernel<<<dim3(8,8,32),256>>>(key, keypre, ke_w);
    // w72 = e2(lrelu(e1([q;key])))   -- fused, no hidden in DRAM
    embed_fused_kernel<<<dim3(128,8),256>>>(q, key, e1_w, e2_w, e2_b, w72);
    // lc = local_conv(v, w72)
    localconv_kernel<false><<<dim3(4,8,64),256>>>(lc, v, w72, nullptr, nullptr, nullptr);
    // attn(raw) = sw2(lrelu(sw1([lc;key]))); softmax deferred to stats+consumer
    embed_fused_kernel<<<dim3(128,8),256>>>(lc, key, sw1_w, sw2_w, sw2_b, attn);
    softmax_stats_kernel<<<dim3(4, 8*72), dim3(32,8)>>>(attn, gmax, ginv);
    // out = local_conv(sec([lc;key]), softmax(attn)) + x
    conv1x1_bf16<128,64,64,0><<<dim3(128,8,1),256>>>(
        lc, key, sec_w, sec_w, sec_w, sec_b, sec_b, sec_b, u, u, u);
    localconv_kernel<true><<<dim3(4,8,64),256>>>(out, u, attn, x, gmax, ginv);
}

// round 17
// speedup vs baseline: 1.0798x; 1.0798x over previous
#include <cuda_runtime.h>
#include <cuda_bf16.h>
#include <math.h>
#include <stdint.h>

#define HWSZ 16384
#define IMG  128

// -------- scratch (static device memory; no runtime allocation) ------------
#define BUF64 8388608ull   // 8*64*16384 floats
#define BUF72 9437184ull
#define SBUF  73728ull     // per-(b,c,w) softmax stats: 8*72*128
static __device__ float g_scratch[4*BUF64 + BUF72 + 2*SBUF];

// ===================== bf16 split-precision MMA helpers =====================
static __device__ __forceinline__ float lrelu(float v){ return v > 0.f ? v : 0.1f*v; }

static __device__ __forceinline__ void bfsplit2(float v0, float v1,
                                                uint32_t& hi, uint32_t& lo){
    __nv_bfloat16 h0 = __float2bfloat16(v0), h1 = __float2bfloat16(v1);
    float r0 = v0 - __bfloat162float(h0);
    float r1 = v1 - __bfloat162float(h1);
    __nv_bfloat162 H = __halves2bfloat162(h0, h1);
    __nv_bfloat162 L = __halves2bfloat162(__float2bfloat16(r0), __float2bfloat16(r1));
    hi = *(uint32_t*)&H;  lo = *(uint32_t*)&L;
}

static __device__ __forceinline__ void mma_bf16(float* c, const uint32_t* a,
                                                uint32_t b0, uint32_t b1){
    asm volatile(
        "mma.sync.aligned.m16n8k16.row.col.f32.bf16.bf16.f32 "
        "{%0,%1,%2,%3}, {%4,%5,%6,%7}, {%8,%9}, {%0,%1,%2,%3};"
        : "+f"(c[0]), "+f"(c[1]), "+f"(c[2]), "+f"(c[3])
        : "r"(a[0]), "r"(a[1]), "r"(a[2]), "r"(a[3]), "r"(b0), "r"(b1));
}

template<int NT>
static __device__ __forceinline__ void mma_chunk(
    const uint32_t* __restrict__ sAh, const uint32_t* __restrict__ sAl,
    const uint32_t* __restrict__ sBh, const uint32_t* __restrict__ sBl,
    int pr, int gid, int tig, float (*acc)[4])
{
    #pragma unroll
    for (int kh = 0; kh < 2; kh++) {
        const int ab = kh*8 + tig;
        uint32_t ah[4], al[4];
        ah[0] = sAh[pr*20 + ab];       ah[1] = sAh[(pr+8)*20 + ab];
        ah[2] = sAh[pr*20 + ab + 4];   ah[3] = sAh[(pr+8)*20 + ab + 4];
        al[0] = sAl[pr*20 + ab];       al[1] = sAl[(pr+8)*20 + ab];
        al[2] = sAl[pr*20 + ab + 4];   al[3] = sAl[(pr+8)*20 + ab + 4];
        #pragma unroll
        for (int nt = 0; nt < NT; nt++) {
            const int nb = (nt*8 + gid)*20 + kh*8 + tig;
            uint32_t bh0 = sBh[nb], bh1 = sBh[nb + 4];
            uint32_t bl0 = sBl[nb], bl1 = sBl[nb + 4];
            mma_bf16(acc[nt], ah, bh0, bh1);
            mma_bf16(acc[nt], al, bh0, bh1);
            mma_bf16(acc[nt], ah, bl0, bl1);
        }
    }
}

static __device__ __forceinline__ void load_a_chunk(
    uint32_t* sAh, uint32_t* sAl, const float* __restrict__ in0,
    const float* __restrict__ in1, int split, int c1,
    int c0, int bat, int p0, int tid)
{
    for (int idx = tid; idx < 2048; idx += 256) {
        int k2 = idx >> 7, p = idx & 127;
        int kg = c0 + 2*k2;
        const float* s = (kg < split)
            ? in0 + ((size_t)bat*split + kg)*HWSZ
            : in1 + ((size_t)bat*c1 + (kg - split))*HWSZ;
        float v0 = s[p0 + p], v1 = s[p0 + p + HWSZ];
        uint32_t hi, lo; bfsplit2(v0, v1, hi, lo);
        sAh[p*20 + k2] = hi;  sAl[p*20 + k2] = lo;
    }
}

static __device__ __forceinline__ void load_b_chunk(
    uint32_t* sBh, uint32_t* sBl, const float* __restrict__ W,
    int N, int KC, int c0, int tid)
{
    for (int idx = tid; idx < N*16; idx += 256) {
        int n = idx >> 4, k2 = idx & 15;
        float v0 = W[n*KC + c0 + 2*k2], v1 = W[n*KC + c0 + 2*k2 + 1];
        uint32_t hi, lo; bfsplit2(v0, v1, hi, lo);
        sBh[n*20 + k2] = hi;  sBl[n*20 + k2] = lo;
    }
}

// ---------------------------------------------------------------------------
// 1x1-conv GEMM body (bf16 split, tensor cores). 128 pixels x N couts.
// (R14 structure: plain load->sync->MMA loop; pipelining regressed in R15.)
// ---------------------------------------------------------------------------
template<int KC, int N, int SPLIT, int ACT>
static __device__ __forceinline__ void conv1x1_body(
    char* smem, const float* __restrict__ in0, const float* __restrict__ in1,
    const float* __restrict__ W, const float* __restrict__ Bb,
    float* __restrict__ O, int bat, int p0, int tid)
{
    constexpr int NT = N/8;
    constexpr int NP = N + 2;
    uint32_t* sAh = (uint32_t*)smem;
    uint32_t* sAl = sAh + 128*20;
    uint32_t* sBh = sAl + 128*20;
    uint32_t* sBl = sBh + N*20;
    float* sOut = (float*)smem;

    const int warp = tid >> 5, lane = tid & 31;
    const int gid = lane >> 2, tig = lane & 3;
    const int pr = warp*16 + gid;

    float acc[NT][4];
    #pragma unroll
    for (int t = 0; t < NT; t++)
        #pragma unroll
        for (int j = 0; j < 4; j++) acc[t][j] = 0.f;

    for (int c0 = 0; c0 < KC; c0 += 32) {
        __syncthreads();
        load_a_chunk(sAh, sAl, in0, in1, SPLIT, KC-SPLIT, c0, bat, p0, tid);
        load_b_chunk(sBh, sBl, W, N, KC, c0, tid);
        __syncthreads();
        mma_chunk<NT>(sAh, sAl, sBh, sBl, pr, gid, tig, acc);
    }
    __syncthreads();
    #pragma unroll
    for (int nt = 0; nt < NT; nt++) {
        int n = nt*8 + 2*tig;
        sOut[pr*NP + n]     = acc[nt][0];  sOut[pr*NP + n + 1]     = acc[nt][1];
        sOut[(pr+8)*NP + n] = acc[nt][2];  sOut[(pr+8)*NP + n + 1] = acc[nt][3];
    }
    __syncthreads();
    for (int idx = tid; idx < N*128; idx += 256) {
        int n = idx >> 7, p = idx & 127;
        float v = sOut[p*NP + n] + (Bb ? Bb[n] : 0.f);
        if (ACT) v = lrelu(v);
        O[((size_t)bat*N + n)*HWSZ + p0 + p] = v;
    }
}

// ---------------------------------------------------------------------------
// Fused embed chain body: O[72] = W2 * lrelu(W1 * [in0;in1]) + b2.
// ---------------------------------------------------------------------------
static __device__ __forceinline__ void embed_body(
    char* smem, const float* __restrict__ in0, const float* __restrict__ in1,
    const float* __restrict__ W1, const float* __restrict__ W2,
    const float* __restrict__ b2, float* __restrict__ O,
    int bat, int p0, int tid)
{
    uint32_t* sAh  = (uint32_t*)smem;
    uint32_t* sAl  = sAh + 128*20;
    uint32_t* sB1h = sAl + 128*20;
    uint32_t* sB1l = sB1h + 32*20;
    uint32_t* sB2h = sAl + 128*20;       // aliases stage-1 B (dead by then)
    uint32_t* sB2l = sB2h + 72*20;
    float* sOut = (float*)smem;

    const int warp = tid >> 5, lane = tid & 31;
    const int gid = lane >> 2, tig = lane & 3;
    const int pr = warp*16 + gid;

    float acc1[4][4];
    #pragma unroll
    for (int t = 0; t < 4; t++)
        #pragma unroll
        for (int j = 0; j < 4; j++) acc1[t][j] = 0.f;

    for (int c0 = 0; c0 < 128; c0 += 32) {
        __syncthreads();
        load_a_chunk(sAh, sAl, in0, in1, 64, 64, c0, bat, p0, tid);
        load_b_chunk(sB1h, sB1l, W1, 32, 128, c0, tid);
        __syncthreads();
        mma_chunk<4>(sAh, sAl, sB1h, sB1l, pr, gid, tig, acc1);
    }
    __syncthreads();

    #pragma unroll
    for (int nt = 0; nt < 4; nt++) {
        uint32_t hi, lo;
        bfsplit2(lrelu(acc1[nt][0]), lrelu(acc1[nt][1]), hi, lo);
        sAh[pr*20 + nt*4 + tig] = hi;  sAl[pr*20 + nt*4 + tig] = lo;
        bfsplit2(lrelu(acc1[nt][2]), lrelu(acc1[nt][3]), hi, lo);
        sAh[(pr+8)*20 + nt*4 + tig] = hi;  sAl[(pr+8)*20 + nt*4 + tig] = lo;
    }
    load_b_chunk(sB2h, sB2l, W2, 72, 32, 0, tid);
    __syncthreads();

    float acc2[9][4];
    #pragma unroll
    for (int t = 0; t < 9; t++)
        #pragma unroll
        for (int j = 0; j < 4; j++) acc2[t][j] = 0.f;
    mma_chunk<9>(sAh, sAl, sB2h, sB2l, pr, gid, tig, acc2);
    __syncthreads();

    #pragma unroll
    for (int nt = 0; nt < 9; nt++) {
        int n = nt*8 + 2*tig;
        sOut[pr*74 + n]     = acc2[nt][0];  sOut[pr*74 + n + 1]     = acc2[nt][1];
        sOut[(pr+8)*74 + n] = acc2[nt][2];  sOut[(pr+8)*74 + n + 1] = acc2[nt][3];
    }
    __syncthreads();
    for (int idx = tid; idx < 72*128; idx += 256) {
        int n = idx >> 7, p = idx & 127;
        float v = sOut[p*74 + n] + b2[n];
        O[((size_t)bat*72 + n)*HWSZ + p0 + p] = v;
    }
}

// ---------------------------------------------------------------------------
// Standalone conv1x1 kernel (fused3 phi/theta/c1 via blockIdx.z).
// ---------------------------------------------------------------------------
template<int KC, int N, int SPLIT, int ACT>
__global__ void __launch_bounds__(256, 4)
conv1x1_bf16(const float* __restrict__ in0, const float* __restrict__ in1,
             const float* __restrict__ w0, const float* __restrict__ w1,
             const float* __restrict__ w2,
             const float* __restrict__ b0, const float* __restrict__ b1,
             const float* __restrict__ b2,
             float* __restrict__ o0, float* __restrict__ o1, float* __restrict__ o2)
{
    constexpr int AB = (256 + 2*N)*80;
    constexpr int ST = 128*(N+2)*4;
    constexpr int SMEMB = AB > ST ? AB : ST;
    __shared__ __align__(16) char smem[SMEMB];
    const int seg = blockIdx.z;
    const float* W  = (seg == 0) ? w0 : (seg == 1) ? w1 : w2;
    const float* Bb = (seg == 0) ? b0 : (seg == 1) ? b1 : b2;
    float*       O  = (seg == 0) ? o0 : (seg == 1) ? o1 : o2;
    conv1x1_body<KC, N, SPLIT, ACT>(smem, in0, in1, W, Bb, O,
                                    blockIdx.y, blockIdx.x*128, threadIdx.x);
}

// ---------------------------------------------------------------------------
// First embed chain (e1->e2), standalone.
// ---------------------------------------------------------------------------
__global__ void __launch_bounds__(256, 4)
embed_fused_kernel(const float* __restrict__ in0, const float* __restrict__ in1,
                   const float* __restrict__ W1, const float* __restrict__ W2,
                   const float* __restrict__ b2, float* __restrict__ O)
{
    __shared__ __align__(16) char smem[37888];
    embed_body(smem, in0, in1, W1, W2, b2, O,
               blockIdx.y, blockIdx.x*128, threadIdx.x);
}

// ---------------------------------------------------------------------------
// MERGED kernel: z=0 -> sw-embed chain (attn raw), z=1 -> sec GEMM (u).
// Both read only lc+key; independent outputs; co-resident CTAs overlap the
// two latency-bound phases and share L2 on the common inputs.
// ---------------------------------------------------------------------------
__global__ void __launch_bounds__(256, 4)
sec_embed_kernel(const float* __restrict__ lc, const float* __restrict__ key,
                 const float* __restrict__ sw1_w, const float* __restrict__ sw2_w,
                 const float* __restrict__ sw2_b,
                 const float* __restrict__ sec_w, const float* __restrict__ sec_b,
                 float* __restrict__ attn, float* __restrict__ u)
{
    __shared__ __align__(16) char smem[37888];   // max(embed 37888, conv 33792)
    const int tid = threadIdx.x, bat = blockIdx.y, p0 = blockIdx.x*128;
    if (blockIdx.z == 0)
        embed_body(smem, lc, key, sw1_w, sw2_w, sw2_b, attn, bat, p0, tid);
    else
        conv1x1_body<128, 64, 64, 0>(smem, lc, key, sec_w, sec_b, u, bat, p0, tid);
}

// ---------------------------------------------------------------------------
// Grouped 3x3 conv (groups=4, 16 in/16 out per group), pad 1, + leaky relu.
// ---------------------------------------------------------------------------
__global__ void __launch_bounds__(256, 5)
convke_kernel(float* __restrict__ out, const float* __restrict__ in,
              const float* __restrict__ w)
{
    const int tid = threadIdx.x;
    const int b = blockIdx.z >> 2, g = blockIdx.z & 3;
    const int x0 = blockIdx.x * 16, y0 = blockIdx.y * 16;
    __shared__ __align__(16) float sv[16][18][18];
    __shared__ __align__(16) float swt[16][9][16];

    for (int i = tid; i < 16*16*9; i += 256) {
        int co = i / 144; int r = i - co*144; int ci = r / 9; int tap = r - ci*9;
        swt[ci][tap][co] = w[((g*16 + co)*16 + ci)*9 + tap];
    }
    for (int i = tid; i < 16*324; i += 256) {
        int ci = i / 324; int r = i - ci*324; int yy = r / 18; int xx = r - yy*18;
        int gy = y0 + yy - 1, gx = x0 + xx - 1;
        float v = 0.f;
        if ((unsigned)gy < 128u && (unsigned)gx < 128u)
            v = in[(((size_t)b*64 + g*16 + ci)*IMG + gy)*IMG + gx];
        sv[ci][yy][xx] = v;
    }
    __syncthreads();

    const int ty = tid >> 4, tx = tid & 15;
    float acc[16];
    #pragma unroll
    for (int c = 0; c < 16; c++) acc[c] = 0.f;

    #pragma unroll
    for (int ci = 0; ci < 16; ci++) {
        float win[9];
        #pragma unroll
        for (int t = 0; t < 9; t++) win[t] = sv[ci][ty + t/3][tx + t%3];
        #pragma unroll
        for (int t = 0; t < 9; t++) {
            #pragma unroll
            for (int q = 0; q < 4; q++) {
                float4 wq = *(const float4*)&swt[ci][t][q*4];
                acc[q*4+0] += win[t]*wq.x;
                acc[q*4+1] += win[t]*wq.y;
                acc[q*4+2] += win[t]*wq.z;
                acc[q*4+3] += win[t]*wq.w;
            }
        }
    }
    #pragma unroll
    for (int co = 0; co < 16; co++) {
        float v = acc[co]; v = v > 0.f ? v : 0.1f*v;
        out[(((size_t)b*64 + g*16 + co)*IMG + y0+ty)*IMG + x0+tx] = v;
    }
}

// ---------------------------------------------------------------------------
// Softmax column stats: per (b,c,w) max and 1/sum(exp(.-max)) over H.
// ---------------------------------------------------------------------------
__global__ void softmax_stats_kernel(const float* __restrict__ a,
                                     float* __restrict__ gmax,
                                     float* __restrict__ ginv)
{
    const int tx = threadIdx.x, ty = threadIdx.y;
    const int w = blockIdx.x*32 + tx;
    const size_t base = (size_t)blockIdx.y * HWSZ + w;   // blockIdx.y = b*72+c
    float vals[16];
    float mx = -3.4e38f;
    #pragma unroll
    for (int i = 0; i < 16; i++) {
        vals[i] = a[base + (size_t)(ty*16 + i)*IMG];
        mx = fmaxf(mx, vals[i]);
    }
    __shared__ float red[8][32];
    red[ty][tx] = mx;
    __syncthreads();
    float m = red[0][tx];
    #pragma unroll
    for (int j = 1; j < 8; j++) m = fmaxf(m, red[j][tx]);
    __syncthreads();
    float s = 0.f;
    #pragma unroll
    for (int i = 0; i < 16; i++) s += __expf(vals[i] - m);
    red[ty][tx] = s;
    __syncthreads();
    if (ty == 0) {
        float tot = 0.f;
        #pragma unroll
        for (int j = 0; j < 8; j++) tot += red[j][tx];
        gmax[(size_t)blockIdx.y*IMG + w] = m;
        ginv[(size_t)blockIdx.y*IMG + w] = 1.f / tot;
    }
}

// ---------------------------------------------------------------------------
// Per-pixel dynamic local conv v3 (32x16 tile, 2 px/thread, occupancy-tuned).
// RESID instance applies softmax normalization (exp(raw-m)*inv) + residual.
// ---------------------------------------------------------------------------
template<bool RESID>
__global__ void __launch_bounds__(256, 6)
localconv_kernel(float* __restrict__ out, const float* __restrict__ v,
                 const float* __restrict__ wd, const float* __restrict__ resid,
                 const float* __restrict__ gmax, const float* __restrict__ ginv)
{
    const int tid = threadIdx.x;
    const int b = blockIdx.z >> 3, cg = blockIdx.z & 7;
    const int x0 = blockIdx.x * 32, y0 = blockIdx.y * 16;
    __shared__ float sv[8][18][35];

    const float* vb = v + ((size_t)(b*64 + cg*8))*HWSZ;
    #pragma unroll
    for (int cl = 0; cl < 8; cl++) {
        for (int i = tid; i < 18*34; i += 256) {
            int yy = i / 34, xx = i - yy*34;
            int gy = y0 + yy - 1, gx = x0 + xx - 1;
            float val = 0.f;
            if ((unsigned)gy < 128u && (unsigned)gx < 128u)
                val = vb[cl*HWSZ + gy*IMG + gx];
            sv[cl][yy][xx] = val;
        }
    }
    __syncthreads();

    const int ty = tid >> 4;            // 0..15
    const int tx = (tid & 15) * 2;      // 0,2,...,30
    const size_t pix = (size_t)(y0 + ty)*IMG + (x0 + tx);

    float2 wt[9];
    const float* wb = wd + ((size_t)(b*72 + cg*9))*HWSZ + pix;
    #pragma unroll
    for (int t = 0; t < 9; t++)
        wt[t] = *(const float2*)(wb + (size_t)t*HWSZ);

    if (RESID) {
        const size_t sb = (size_t)(b*72 + cg*9)*IMG + (x0 + tx);
        #pragma unroll
        for (int t = 0; t < 9; t++) {
            const float2 m  = *(const float2*)(gmax + sb + (size_t)t*IMG);
            const float2 iv = *(const float2*)(ginv + sb + (size_t)t*IMG);
            wt[t].x = __expf(wt[t].x - m.x) * iv.x;
            wt[t].y = __expf(wt[t].y - m.y) * iv.y;
        }
    }

    float* ob = out + ((size_t)(b*64 + cg*8))*HWSZ + pix;
    const float* rb = RESID ? resid + ((size_t)(b*64 + cg*8))*HWSZ + pix : nullptr;

    #pragma unroll
    for (int cl = 0; cl < 8; cl++) {
        float a0 = 0.f, a1 = 0.f;
        #pragma unroll
        for (int r = 0; r < 3; r++) {
            float vr[4];
            #pragma unroll
            for (int j = 0; j < 4; j++) vr[j] = sv[cl][ty + r][tx + j];
            #pragma unroll
            for (int c = 0; c < 3; c++) {
                const float2 w = wt[r*3 + c];
                a0 += vr[c]     * w.x;
                a1 += vr[c + 1] * w.y;
            }
        }
        float2 o = make_float2(a0, a1);
        if (RESID) {
            const float2 rr = *(const float2*)(rb + (size_t)cl*HWSZ);
            o.x += rr.x; o.y += rr.y;
        }
        *(float2*)(ob + (size_t)cl*HWSZ) = o;
    }
}

// ---------------------------------------------------------------------------
extern "C" void kernel_launch(void* const* d_in, const int* in_sizes, int n_in,
                              void* d_out, int out_size)
{
    const float* x      = (const float*)d_in[0];
    const float* phi_w  = (const float*)d_in[1];
    const float* phi_b  = (const float*)d_in[2];
    const float* theta_w= (const float*)d_in[3];
    const float* theta_b= (const float*)d_in[4];
    const float* ke_w   = (const float*)d_in[5];
    const float* e1_w   = (const float*)d_in[6];
    const float* e2_w   = (const float*)d_in[7];
    const float* e2_b   = (const float*)d_in[8];
    const float* c1_w   = (const float*)d_in[9];
    const float* sw1_w  = (const float*)d_in[10];
    const float* sw2_w  = (const float*)d_in[11];
    const float* sw2_b  = (const float*)d_in[12];
    const float* sec_w  = (const float*)d_in[13];
    const float* sec_b  = (const float*)d_in[14];
    float* out = (float*)d_out;

    float* base = nullptr;
    cudaGetSymbolAddress((void**)&base, g_scratch);
    float* q      = base;              // -> lc
    float* v      = base + BUF64;
    float* keypre = base + 2*BUF64;    // -> u
    float* key    = base + 3*BUF64;
    float* w72    = base + 4*BUF64;    // -> attn(raw)
    float* gmax   = base + 4*BUF64 + BUF72;
    float* ginv   = gmax + SBUF;
    float* lc   = q;
    float* u    = keypre;
    float* attn = w72;

    // fused (by grid.z): keypre = phi(x)+b | q = theta(x)+b | v = c1(x)
    conv1x1_bf16<64,64,64,0><<<dim3(128,8,3),256>>>(
        x, nullptr, phi_w, theta_w, c1_w, phi_b, theta_b, nullptr,
        keypre, q, v);
    // key = lrelu(grouped 3x3(keypre))
    convke_kernel<<<dim3(8,8,32),256>>>(key, keypre, ke_w);
    // w72 = e2(lrelu(e1([q;key])))   -- fused, no hidden in DRAM
    embed_fused_kernel<<<dim3(128,8),256>>>(q, key, e1_w, e2_w, e2_b, w72);
    // lc = local_conv(v, w72)
    localconv_kernel<false><<<dim3(4,8,64),256>>>(lc, v, w72, nullptr, nullptr, nullptr);
    // MERGED: attn(raw) = sw2(lrelu(sw1([lc;key])))  ||  u = sec([lc;key])+b
    sec_embed_kernel<<<dim3(128,8,2),256>>>(
        lc, key, sw1_w, sw2_w, sw2_b, sec_w, sec_b, attn, u);
    softmax_stats_kernel<<<dim3(4, 8*72), dim3(32,8)>>>(attn, gmax, ginv);
    // out = local_conv(u, softmax(attn)) + x
    localconv_kernel<true><<<dim3(4,8,64),256>>>(out, u, attn, x, gmax, ginv);
}